// round 13
// baseline (speedup 1.0000x reference)
#include <cuda_runtime.h>

#define NBLK  296              // 148 SMs x 2 resident CTAs
#define NTHR  512
#define CHUNK 2048LL           // float4 per chunk = 32 KB
#define BUFCH 3                // chunks buffered in smem per CTA (96 KB)
#define BUFTOT (BUFCH * NBLK)  // 888 low chunks held in smem chip-wide (~28 MB)

// Scratch (no allocations). State overwritten each run, wraps (g_count), or is
// monotonic with entry-captured baseline (g_epoch) -> graph-replay safe.
__device__ double                g_partials[NBLK];
__device__ float                 g_total;
__device__ unsigned int          g_count;
__device__ volatile unsigned int g_epoch;

__global__ void __launch_bounds__(NTHR, 2) fused_kernel(const float4* __restrict__ x4,
                                                        float4* __restrict__ out4,
                                                        long long n4)
{
    extern __shared__ float4 sbuf[];               // BUFCH * CHUNK float4 = 96 KB

    const long long nch     = n4 / CHUNK;          // 8192 for 8192^2
    const long long n4_main = nch * CHUNK;
    const long long tid     = (long long)blockIdx.x * blockDim.x + threadIdx.x;
    const long long gstride = (long long)gridDim.x * blockDim.x;

    const unsigned epoch0 = g_epoch;   // capture before any arrival can fire

    // This CTA's residue class: chunks c with c % NBLK == r are its chunks.
    const long long r = ((nch - 1 - (long long)blockIdx.x) % NBLK + NBLK) % NBLK;

    // -------- Phase 1: reduction, chunks walked DESCENDING ------------------
    // The final BUFCH chunks (c < BUFTOT, the lowest addresses) are also
    // copied into smem: phase 2 reads them with zero LTS/DRAM traffic.
    float s0=0.f, s1=0.f, s2=0.f, s3=0.f;

    for (long long c = nch - 1 - blockIdx.x; c >= 0; c -= NBLK) {
        const float4* base = x4 + c * CHUNK + threadIdx.x;
        float4 v0 = base[0];
        float4 v1 = base[512];
        float4 v2 = base[1024];
        float4 v3 = base[1536];
        if (c < BUFTOT) {                          // stash in smem (slot c/NBLK)
            float4* b = sbuf + (c / NBLK) * CHUNK + threadIdx.x;
            b[0]    = v0;
            b[512]  = v1;
            b[1024] = v2;
            b[1536] = v3;
        }
        s0 += (v0.x + v0.y) + (v0.z + v0.w);
        s1 += (v1.x + v1.y) + (v1.z + v1.w);
        s2 += (v2.x + v2.y) + (v2.z + v2.w);
        s3 += (v3.x + v3.y) + (v3.z + v3.w);
    }
    for (long long i = n4_main + tid; i < n4; i += gstride) {   // tail (empty here)
        float4 v = x4[i];
        s0 += (v.x + v.y) + (v.z + v.w);
    }

    double acc = ((double)s0 + (double)s1) + ((double)s2 + (double)s3);

    __shared__ double sdata[NTHR];
    sdata[threadIdx.x] = acc;
    __syncthreads();
    for (int s = NTHR/2; s > 0; s >>= 1) {
        if (threadIdx.x < s) sdata[threadIdx.x] += sdata[threadIdx.x + s];
        __syncthreads();
    }

    // -------- Arrival + last-block finalize ---------------------------------
    __shared__ bool s_isLast;
    if (threadIdx.x == 0) {
        g_partials[blockIdx.x] = sdata[0];
        __threadfence();
        unsigned v = atomicInc(&g_count, gridDim.x - 1);   // wraps -> replay-safe
        s_isLast = (v == gridDim.x - 1);
    }
    __syncthreads();

    if (s_isLast) {
        double facc = 0.0;
        for (int k = threadIdx.x; k < NBLK; k += NTHR) facc += g_partials[k];
        sdata[threadIdx.x] = facc;
        __syncthreads();
        for (int s = NTHR/2; s > 0; s >>= 1) {
            if (threadIdx.x < s) sdata[threadIdx.x] += sdata[threadIdx.x + s];
            __syncthreads();
        }
        if (threadIdx.x == 0) {
            float  sf = (float)sdata[0];        // mimic jnp.sum's fp32 result
            double nn = trunc((double)sf);
            double tt = (nn > 1.0) ? nn * (nn - 1.0) * 0.5 : 0.0;
            g_total = (float)tt;
            __threadfence();
            g_epoch = g_epoch + 1;              // release
        }
        __syncthreads();
    } else {
        if (threadIdx.x == 0) {
            while (g_epoch == epoch0) { __nanosleep(64); }
            __threadfence();
        }
        __syncthreads();
    }

    __shared__ float s_t;
    if (threadIdx.x == 0) s_t = g_total;
    __syncthreads();
    const float t = s_t;

    // -------- Phase 2a: drain smem-buffered chunks (no global reads) --------
    // Chunk c = r + s*NBLK for slot s, covering every c in [0, BUFTOT) chip-
    // wide. Writes only -> LTS sees half the usual phase-2 traffic here.
    #pragma unroll
    for (int s = 0; s < BUFCH; s++) {
        const long long c = r + (long long)s * NBLK;
        if (c < nch && c < BUFTOT) {
            const float4* b = sbuf + (long long)s * CHUNK + threadIdx.x;
            float4*     dst = out4 + c * CHUNK + threadIdx.x;
            float4 v0 = b[0];
            float4 v1 = b[512];
            float4 v2 = b[1024];
            float4 v3 = b[1536];
            v0.x += t; v0.y += t; v0.z += t; v0.w += t;
            v1.x += t; v1.y += t; v1.z += t; v1.w += t;
            v2.x += t; v2.y += t; v2.z += t; v2.w += t;
            v3.x += t; v3.y += t; v3.z += t; v3.w += t;
            __stcs(dst,        v0);
            __stcs(dst + 512,  v1);
            __stcs(dst + 1024, v2);
            __stcs(dst + 1536, v3);
        }
    }

    // -------- Phase 2b: remaining chunks ASCENDING from BUFTOT --------------
    // First reads hit the phase-1 L2 residue just above the smem-covered
    // region. __ldcs/__stcs avoid polluting it.
    for (long long c = BUFTOT + blockIdx.x; c < nch; c += NBLK) {
        const float4* src = x4   + c * CHUNK + threadIdx.x;
        float4*       dst = out4 + c * CHUNK + threadIdx.x;
        float4 v0 = __ldcs(src);
        float4 v1 = __ldcs(src + 512);
        float4 v2 = __ldcs(src + 1024);
        float4 v3 = __ldcs(src + 1536);
        v0.x += t; v0.y += t; v0.z += t; v0.w += t;
        v1.x += t; v1.y += t; v1.z += t; v1.w += t;
        v2.x += t; v2.y += t; v2.z += t; v2.w += t;
        v3.x += t; v3.y += t; v3.z += t; v3.w += t;
        __stcs(dst,        v0);
        __stcs(dst + 512,  v1);
        __stcs(dst + 1024, v2);
        __stcs(dst + 1536, v3);
    }
    for (long long i = n4_main + tid; i < n4; i += gstride) {   // tail (empty here)
        float4 v = __ldcs(&x4[i]);
        v.x += t; v.y += t; v.z += t; v.w += t;
        __stcs(&out4[i], v);
    }
}

extern "C" void kernel_launch(void* const* d_in, const int* in_sizes, int n_in,
                              void* d_out, int out_size)
{
    const float4* x4   = (const float4*)d_in[0];
    float4*       out4 = (float4*)d_out;
    long long n  = (long long)in_sizes[0];   // 8192*8192
    long long n4 = n >> 2;

    const int smem_bytes = (int)(BUFCH * CHUNK * sizeof(float4));   // 96 KB
    static bool attr_done = false;           // host-side idempotent attr set
    if (!attr_done) {
        cudaFuncSetAttribute(fused_kernel,
                             cudaFuncAttributeMaxDynamicSharedMemorySize, smem_bytes);
        attr_done = true;
    }
    fused_kernel<<<NBLK, NTHR, smem_bytes>>>(x4, out4, n4);
}

// round 14
// speedup vs baseline: 1.1361x; 1.1361x over previous
#include <cuda_runtime.h>

#define NBLK 296               // 148 SMs x 2 resident CTAs (best measured config)
#define NTHR 512
#define CHUNK 2048LL           // float4 per chunk = 32 KB
#define CHUNK_BYTES 32768

// Scratch (no allocations). State overwritten each run, wraps (g_count), or is
// monotonic with entry-captured baseline (g_epoch) -> graph-replay safe.
__device__ double                g_partials[NBLK];
__device__ float                 g_total;
__device__ unsigned int          g_count;
__device__ volatile unsigned int g_epoch;

__device__ __forceinline__ unsigned smem_u32(const void* p) {
    unsigned a;
    asm("{ .reg .u64 t; cvta.to.shared.u64 t, %1; cvt.u32.u64 %0, t; }"
        : "=r"(a) : "l"(p));
    return a;
}

__global__ void __launch_bounds__(NTHR, 2) fused_kernel(const float4* __restrict__ x4,
                                                        float4* __restrict__ out4,
                                                        long long n4)
{
    extern __shared__ float4 sbuf[];               // 2 x CHUNK float4 = 64 KB

    const long long nch     = n4 / CHUNK;          // 8192 for 8192^2
    const long long n4_main = nch * CHUNK;
    const long long tid     = (long long)blockIdx.x * blockDim.x + threadIdx.x;
    const long long gstride = (long long)gridDim.x * blockDim.x;

    const unsigned epoch0 = g_epoch;   // capture before any arrival can fire

    // -------- Phase 1: reduction, chunks DESCENDING, 2 chunks/iteration -----
    // 8 front-batched LDG.128 per warp per iteration (deeper latency hiding
    // than the 4-deep variant that capped at 5.9 TB/s). Lowest-address chunks
    // are still read last chip-wide -> maximal L2 residue for phase 2.
    float s0=0.f, s1=0.f, s2=0.f, s3=0.f;

    long long c = nch - 1 - (long long)blockIdx.x;
    for (; c >= NBLK; c -= 2*NBLK) {
        const float4* pa = x4 + c * CHUNK + threadIdx.x;
        const float4* pb = x4 + (c - NBLK) * CHUNK + threadIdx.x;
        float4 a0 = pa[0];
        float4 a1 = pa[512];
        float4 a2 = pa[1024];
        float4 a3 = pa[1536];
        float4 b0 = pb[0];
        float4 b1 = pb[512];
        float4 b2 = pb[1024];
        float4 b3 = pb[1536];
        s0 += (a0.x + a0.y) + (a0.z + a0.w);
        s1 += (a1.x + a1.y) + (a1.z + a1.w);
        s2 += (a2.x + a2.y) + (a2.z + a2.w);
        s3 += (a3.x + a3.y) + (a3.z + a3.w);
        s0 += (b0.x + b0.y) + (b0.z + b0.w);
        s1 += (b1.x + b1.y) + (b1.z + b1.w);
        s2 += (b2.x + b2.y) + (b2.z + b2.w);
        s3 += (b3.x + b3.y) + (b3.z + b3.w);
    }
    if (c >= 0) {
        const float4* pa = x4 + c * CHUNK + threadIdx.x;
        float4 a0 = pa[0];
        float4 a1 = pa[512];
        float4 a2 = pa[1024];
        float4 a3 = pa[1536];
        s0 += (a0.x + a0.y) + (a0.z + a0.w);
        s1 += (a1.x + a1.y) + (a1.z + a1.w);
        s2 += (a2.x + a2.y) + (a2.z + a2.w);
        s3 += (a3.x + a3.y) + (a3.z + a3.w);
    }
    for (long long i = n4_main + tid; i < n4; i += gstride) {   // tail (empty here)
        float4 v = x4[i];
        s0 += (v.x + v.y) + (v.z + v.w);
    }

    double acc = ((double)s0 + (double)s1) + ((double)s2 + (double)s3);

    __shared__ double sdata[NTHR];
    sdata[threadIdx.x] = acc;
    __syncthreads();
    for (int s = NTHR/2; s > 0; s >>= 1) {
        if (threadIdx.x < s) sdata[threadIdx.x] += sdata[threadIdx.x + s];
        __syncthreads();
    }

    // -------- Arrival + last-block finalize ---------------------------------
    __shared__ bool s_isLast;
    if (threadIdx.x == 0) {
        g_partials[blockIdx.x] = sdata[0];
        __threadfence();
        unsigned v = atomicInc(&g_count, gridDim.x - 1);   // wraps -> replay-safe
        s_isLast = (v == gridDim.x - 1);
    }
    __syncthreads();

    if (s_isLast) {
        double facc = 0.0;
        for (int k = threadIdx.x; k < NBLK; k += NTHR) facc += g_partials[k];
        sdata[threadIdx.x] = facc;
        __syncthreads();
        for (int s = NTHR/2; s > 0; s >>= 1) {
            if (threadIdx.x < s) sdata[threadIdx.x] += sdata[threadIdx.x + s];
            __syncthreads();
        }
        if (threadIdx.x == 0) {
            float  sf = (float)sdata[0];        // mimic jnp.sum's fp32 result
            double nn = trunc((double)sf);
            double tt = (nn > 1.0) ? nn * (nn - 1.0) * 0.5 : 0.0;
            g_total = (float)tt;
            __threadfence();
            g_epoch = g_epoch + 1;              // release
        }
        __syncthreads();
    } else {
        if (threadIdx.x == 0) {
            while (g_epoch == epoch0) { __nanosleep(64); }
            __threadfence();
        }
        __syncthreads();
    }

    __shared__ float s_t;
    if (threadIdx.x == 0) s_t = g_total;
    __syncthreads();
    const float t = s_t;

    // -------- Phase 2: out = x + t, ASCENDING, ASYNC BULK STORES ------------
    // (R12 structure — best measured phase 2.) Loads via __ldcs don't pollute
    // the phase-1 residue; results staged in smem, stored by one 32KB
    // cp.async.bulk per chunk with evict_first policy, double-buffered.
    unsigned long long pol;
    asm("createpolicy.fractional.L2::evict_first.b64 %0, 1.0;" : "=l"(pol));

    long long it = 0;
    for (long long cc = blockIdx.x; cc < nch; cc += NBLK, it++) {
        const float4* src = x4 + cc * CHUNK + threadIdx.x;
        float4 v0 = __ldcs(src);
        float4 v1 = __ldcs(src + 512);
        float4 v2 = __ldcs(src + 1024);
        float4 v3 = __ldcs(src + 1536);
        v0.x += t; v0.y += t; v0.z += t; v0.w += t;
        v1.x += t; v1.y += t; v1.z += t; v1.w += t;
        v2.x += t; v2.y += t; v2.z += t; v2.w += t;
        v3.x += t; v3.y += t; v3.z += t; v3.w += t;

        if (threadIdx.x == 0)
            asm volatile("cp.async.bulk.wait_group 1;" ::: "memory");
        __syncthreads();

        float4* b = sbuf + (it & 1) * CHUNK;
        b[threadIdx.x]        = v0;
        b[threadIdx.x + 512]  = v1;
        b[threadIdx.x + 1024] = v2;
        b[threadIdx.x + 1536] = v3;
        asm volatile("fence.proxy.async.shared::cta;" ::: "memory");
        __syncthreads();

        if (threadIdx.x == 0) {
            const float4* gdst = out4 + cc * CHUNK;
            unsigned saddr = smem_u32(b);
            asm volatile(
                "cp.async.bulk.global.shared::cta.bulk_group.L2::cache_hint "
                "[%0], [%1], %2, %3;"
                :: "l"(gdst), "r"(saddr), "r"((unsigned)CHUNK_BYTES), "l"(pol)
                : "memory");
            asm volatile("cp.async.bulk.commit_group;" ::: "memory");
        }
    }
    if (threadIdx.x == 0)
        asm volatile("cp.async.bulk.wait_group 0;" ::: "memory");
    __syncthreads();

    for (long long i = n4_main + tid; i < n4; i += gstride) {   // tail (empty here)
        float4 v = __ldcs(&x4[i]);
        v.x += t; v.y += t; v.z += t; v.w += t;
        __stcs(&out4[i], v);
    }
}

extern "C" void kernel_launch(void* const* d_in, const int* in_sizes, int n_in,
                              void* d_out, int out_size)
{
    const float4* x4   = (const float4*)d_in[0];
    float4*       out4 = (float4*)d_out;
    long long n  = (long long)in_sizes[0];   // 8192*8192
    long long n4 = n >> 2;

    static bool attr_done = false;           // host-side idempotent attr set
    if (!attr_done) {
        cudaFuncSetAttribute(fused_kernel,
                             cudaFuncAttributeMaxDynamicSharedMemorySize, 65536);
        attr_done = true;
    }
    fused_kernel<<<NBLK, NTHR, 65536>>>(x4, out4, n4);
}